// round 12
// baseline (speedup 1.0000x reference)
#include <cuda_runtime.h>
#include <cuda_bf16.h>

#define NIDS    33                 // ids 0..32 (0 = background)
#define NBINS   1089               // 33*33
#define THREADS 512
#define NREP    32                 // replicated global histograms (L2-resident, 139 KB)

// Scratch (zero at load; finalize block resets after every call)
__device__ int          g_rep[NREP][NBINS];
__device__ unsigned int g_ticket;

__global__ void __launch_bounds__(THREADS, 3)
fused_iou_kernel(const float4* __restrict__ p4, const float4* __restrict__ t4,
                 int n4,
                 const float* __restrict__ pf, const float* __restrict__ tf,
                 int n, float* __restrict__ out, int nblocks)
{
    __shared__ int   sh[NBINS];
    __shared__ float psum[NIDS], tsum[NIDS], part[NIDS];
    __shared__ int   s_last;

    int tid = threadIdx.x;
    for (int b = tid; b < NBINS; b += THREADS) sh[b] = 0;
    __syncthreads();

    int gid    = blockIdx.x * THREADS + tid;
    int stride = gridDim.x * THREADS;
    int rep    = blockIdx.x & (NREP - 1);
    int* grep  = g_rep[rep];

    // ---- main loop: x,z -> smem ATOMS unit; y,w -> L2 REDG unit (overlap) ----
    int i = gid;
    for (; i + 2 * stride < n4; i += 3 * stride) {
        float4 P0 = p4[i];
        float4 T0 = t4[i];
        float4 P1 = p4[i + stride];
        float4 T1 = t4[i + stride];
        float4 P2 = p4[i + 2 * stride];
        float4 T2 = t4[i + 2 * stride];
        atomicAdd(&sh[(int)fmaf(P0.x, 33.0f, T0.x)], 1);      // bin = 33*p + t (exact fp32)
        atomicAdd(&grep[(int)fmaf(P0.y, 33.0f, T0.y)], 1);    // fire-and-forget RED.E.ADD
        atomicAdd(&sh[(int)fmaf(P0.z, 33.0f, T0.z)], 1);
        atomicAdd(&grep[(int)fmaf(P0.w, 33.0f, T0.w)], 1);
        atomicAdd(&sh[(int)fmaf(P1.x, 33.0f, T1.x)], 1);
        atomicAdd(&grep[(int)fmaf(P1.y, 33.0f, T1.y)], 1);
        atomicAdd(&sh[(int)fmaf(P1.z, 33.0f, T1.z)], 1);
        atomicAdd(&grep[(int)fmaf(P1.w, 33.0f, T1.w)], 1);
        atomicAdd(&sh[(int)fmaf(P2.x, 33.0f, T2.x)], 1);
        atomicAdd(&grep[(int)fmaf(P2.y, 33.0f, T2.y)], 1);
        atomicAdd(&sh[(int)fmaf(P2.z, 33.0f, T2.z)], 1);
        atomicAdd(&grep[(int)fmaf(P2.w, 33.0f, T2.w)], 1);
    }
    for (; i < n4; i += stride) {
        float4 P = p4[i], T = t4[i];
        atomicAdd(&sh[(int)fmaf(P.x, 33.0f, T.x)], 1);
        atomicAdd(&grep[(int)fmaf(P.y, 33.0f, T.y)], 1);
        atomicAdd(&sh[(int)fmaf(P.z, 33.0f, T.z)], 1);
        atomicAdd(&grep[(int)fmaf(P.w, 33.0f, T.w)], 1);
    }
    __syncthreads();

    // ---- flush block-private smem hist into the replicated global hists ----
    for (int b = tid; b < NBINS; b += THREADS) {
        int v = sh[b];
        if (v) atomicAdd(&grep[b], v);
    }
    __threadfence();

    // ---- ticket: last block finalizes ----
    if (tid == 0) {
        unsigned int t = atomicAdd(&g_ticket, 1u);
        s_last = (t == (unsigned int)(nblocks - 1));
    }
    __syncthreads();
    if (!s_last) return;

    // reuse sh as the final histogram
    for (int b = tid; b < NBINS; b += THREADS) {
        int s = 0;
        #pragma unroll
        for (int r = 0; r < NREP; r++) { s += g_rep[r][b]; g_rep[r][b] = 0; }
        sh[b] = s;
    }
    __syncthreads();
    if (tid == 0) {
        for (int k = n4 * 4; k < n; k++)               // scalar tail (n % 4)
            sh[(int)fmaf(pf[k], 33.0f, tf[k])]++;
        g_ticket = 0u;
    }
    __syncthreads();

    if (tid < NIDS) {
        int s = 0;
        #pragma unroll
        for (int m = 0; m < NIDS; m++) s += sh[tid * NIDS + m];
        psum[tid] = (float)s;
    } else if (tid >= 64 && tid < 64 + NIDS) {
        int m = tid - 64, s = 0;
        #pragma unroll
        for (int nn = 0; nn < NIDS; nn++) s += sh[nn * NIDS + m];
        tsum[m] = (float)s;
    }
    __syncthreads();

    if (tid >= 1 && tid <= 32) {
        float pn = psum[tid];
        float max_iou = 0.0f;
        #pragma unroll
        for (int m = 1; m < NIDS; m++) {
            float inter = (float)sh[tid * NIDS + m];
            float uni   = pn + tsum[m] - inter;
            float iou   = (uni > 0.0f) ? (inter / uni) : 0.0f;
            max_iou = fmaxf(max_iou, iou);
        }
        part[tid] = 1.0f - max_iou;
    }
    __syncthreads();

    if (tid == 0) {
        float loss = 0.0f;
        for (int nn = 1; nn <= 32; nn++) loss += part[nn];
        double sp = 0.0, st = 0.0;                      // exact dummy term
        for (int id = 1; id < NIDS; id++) {
            sp += (double)id * (double)psum[id];
            st += (double)id * (double)tsum[id];
        }
        loss += (float)((sp + st) * 1e-12);
        out[0] = loss;
    }
}

extern "C" void kernel_launch(void* const* d_in, const int* in_sizes, int n_in,
                              void* d_out, int out_size) {
    const float* pred  = (const float*)d_in[0];
    const float* truem = (const float*)d_in[1];
    float* out = (float*)d_out;
    int n  = in_sizes[0];
    int n4 = n / 4;

    int sm_count = 148;
    cudaDeviceGetAttribute(&sm_count, cudaDevAttrMultiProcessorCount, 0);
    int blocks = sm_count * 3;   // 3 CTAs/SM x 512 thr = 48 warps/SM (R7 config)

    fused_iou_kernel<<<blocks, THREADS>>>(
        (const float4*)pred, (const float4*)truem, n4,
        pred, truem, n, out, blocks);
}

// round 13
// speedup vs baseline: 1.8792x; 1.8792x over previous
#include <cuda_runtime.h>
#include <cuda_bf16.h>

#define NIDS    33                      // ids 0..32 (0 = background)
#define NBINS   1089                    // 33*33
#define THREADS 1024                    // 32 warps, 1 CTA/SM (smem-limited)
#define NREP    16                      // replicated global histograms
#define SMEM_DYN (NBINS * 128)          // u8[bin][lane][slot0..3] = 139,392 B

// Scratch (zero at load; finalize block resets after every call)
__device__ int          g_rep[NREP][NBINS];
__device__ unsigned int g_ticket;

__global__ void __launch_bounds__(THREADS, 1)
fused_iou_kernel(const float4* __restrict__ p4, const float4* __restrict__ t4,
                 int n4,
                 const float* __restrict__ pf, const float* __restrict__ tf,
                 int n, float* __restrict__ out, int nblocks)
{
    extern __shared__ unsigned char cnt[];   // byte addr = bin*128 + lane*4 + slot
                                             // word = bin*32 + lane -> bank = lane (conflict-free)
    __shared__ float psum[NIDS], tsum[NIDS], part[NIDS];
    __shared__ int   s_last;

    int tid  = threadIdx.x;
    int lane = tid & 31;
    int slot = lane * 4 + ((tid >> 5) & 3);  // 8 warps share each byte slot (benign races)

    // ---- zero byte counters ----
    {
        uint4* z4 = (uint4*)cnt;
        #pragma unroll 3
        for (int i = tid; i < SMEM_DYN / 16; i += THREADS)
            z4[i] = make_uint4(0u, 0u, 0u, 0u);
    }
    __syncthreads();

    int gid    = blockIdx.x * THREADS + tid;
    int stride = gridDim.x * THREADS;

    // ---- main loop: register double-buffered loads + conflict-free byte RMW ----
    int i = gid;
    if (i < n4) {
        float4 P = p4[i], T = t4[i];
        for (; i + stride < n4; ) {
            float4 Pn = p4[i + stride];              // prefetch next (overlaps RMW below)
            float4 Tn = t4[i + stride];

            int i0 = ((int)fmaf(P.x, 33.0f, T.x)) * 128 + slot;   // bin = 33*p + t
            int i1 = ((int)fmaf(P.y, 33.0f, T.y)) * 128 + slot;
            int i2 = ((int)fmaf(P.z, 33.0f, T.z)) * 128 + slot;
            int i3 = ((int)fmaf(P.w, 33.0f, T.w)) * 128 + slot;
            unsigned char a0 = cnt[i0], a1 = cnt[i1], a2 = cnt[i2], a3 = cnt[i3];
            cnt[i0] = a0 + 1; cnt[i1] = a1 + 1; cnt[i2] = a2 + 1; cnt[i3] = a3 + 1;

            P = Pn; T = Tn;
            i += stride;
        }
        // last quad
        int i0 = ((int)fmaf(P.x, 33.0f, T.x)) * 128 + slot;
        int i1 = ((int)fmaf(P.y, 33.0f, T.y)) * 128 + slot;
        int i2 = ((int)fmaf(P.z, 33.0f, T.z)) * 128 + slot;
        int i3 = ((int)fmaf(P.w, 33.0f, T.w)) * 128 + slot;
        unsigned char a0 = cnt[i0], a1 = cnt[i1], a2 = cnt[i2], a3 = cnt[i3];
        cnt[i0] = a0 + 1; cnt[i1] = a1 + 1; cnt[i2] = a2 + 1; cnt[i3] = a3 + 1;
    }
    __syncthreads();

    // ---- flush: warp per bin; lane reads word bin*32+lane (bank = lane) ----
    int w   = tid >> 5;
    int rep = blockIdx.x & (NREP - 1);
    const unsigned int* cw = (const unsigned int*)cnt;
    for (int b = w; b < NBINS; b += 32) {
        unsigned int v   = cw[b * 32 + lane];
        unsigned int s   = __dp4a(v, 0x01010101u, 0u);     // sum 4 slot bytes
        unsigned int tot = __reduce_add_sync(0xffffffffu, s);
        if (lane == 0 && tot)
            atomicAdd(&g_rep[rep][b], (int)tot);
    }
    __threadfence();

    // ---- ticket: last block finalizes ----
    if (tid == 0) {
        unsigned int t = atomicAdd(&g_ticket, 1u);
        s_last = (t == (unsigned int)(nblocks - 1));
    }
    __syncthreads();
    if (!s_last) return;

    int* h = (int*)cnt;   // reuse dynamic smem for the final histogram

    for (int b = tid; b < NBINS; b += THREADS) {
        int s = 0;
        #pragma unroll
        for (int r = 0; r < NREP; r++) { s += g_rep[r][b]; g_rep[r][b] = 0; }
        h[b] = s;
    }
    __syncthreads();
    if (tid == 0) {
        for (int k = n4 * 4; k < n; k++)               // scalar tail (n % 4)
            h[(int)fmaf(pf[k], 33.0f, tf[k])]++;
        g_ticket = 0u;
    }
    __syncthreads();

    if (tid < NIDS) {
        int s = 0;
        #pragma unroll
        for (int m = 0; m < NIDS; m++) s += h[tid * NIDS + m];
        psum[tid] = (float)s;
    } else if (tid >= 64 && tid < 64 + NIDS) {
        int m = tid - 64, s = 0;
        #pragma unroll
        for (int nn = 0; nn < NIDS; nn++) s += h[nn * NIDS + m];
        tsum[m] = (float)s;
    }
    __syncthreads();

    if (tid >= 1 && tid <= 32) {
        float pn = psum[tid];
        float max_iou = 0.0f;
        #pragma unroll
        for (int m = 1; m < NIDS; m++) {
            float inter = (float)h[tid * NIDS + m];
            float uni   = pn + tsum[m] - inter;
            float iou   = (uni > 0.0f) ? (inter / uni) : 0.0f;
            max_iou = fmaxf(max_iou, iou);
        }
        part[tid] = 1.0f - max_iou;
    }
    __syncthreads();

    if (tid == 0) {
        float loss = 0.0f;
        for (int nn = 1; nn <= 32; nn++) loss += part[nn];
        double sp = 0.0, st = 0.0;                      // dummy term
        for (int id = 1; id < NIDS; id++) {
            sp += (double)id * (double)psum[id];
            st += (double)id * (double)tsum[id];
        }
        loss += (float)((sp + st) * 1e-12);
        out[0] = loss;
    }
}

extern "C" void kernel_launch(void* const* d_in, const int* in_sizes, int n_in,
                              void* d_out, int out_size) {
    const float* pred  = (const float*)d_in[0];
    const float* truem = (const float*)d_in[1];
    float* out = (float*)d_out;
    int n  = in_sizes[0];
    int n4 = n / 4;

    cudaFuncSetAttribute(fused_iou_kernel,
                         cudaFuncAttributeMaxDynamicSharedMemorySize, SMEM_DYN);

    int sm_count = 148;
    cudaDeviceGetAttribute(&sm_count, cudaDevAttrMultiProcessorCount, 0);
    int blocks = sm_count;   // 1 CTA/SM (139 KB smem), 1024 threads = 32 warps/SM

    fused_iou_kernel<<<blocks, THREADS, SMEM_DYN>>>(
        (const float4*)pred, (const float4*)truem, n4,
        pred, truem, n, out, blocks);
}